// round 7
// baseline (speedup 1.0000x reference)
#include <cuda_runtime.h>
#include <cuda_bf16.h>
#include <cstddef>

// B=32, T=32768, K=N=8, D=256 — fully fused single-kernel GCAN loss.
// Streaming pass decomposition:
//   nlp = softplus(-x); p2 = sigmoid(x)^2
//   u = 4*nlp - x ; w = p2*x
//   A[k][n] = sum u*y ; W[k][n] = sum w*y   (mma.m16n8k16 bf16, u/w rows stacked)
//   S1[k] = sum (nlp+x) ; S2[k] = sum p2*(nlp+0.9x)
//   cost = (S1+A)/T ; assign_k = 0.75*(S2[k] - 0.8*W[k][col_k])
// Epilogue fused via last-arrival counters (never reset; modulo detection).
// Arrival protocol: block stores -> __syncthreads() -> tid0 fence+atomic.

#define FULLMASK 0xffffffffu
#define CHUNKS 16
#define TPB_T 2048
#define SLOT 145   // 64 A + 64 W + 8 S1 + 8 S2 + 1 overlap

__device__ float gPart[32 * CHUNKS * SLOT];
__device__ float gGram[32 * 40];      // [0..35] gram upper-tri, [36] existence sum
__device__ float gOut[32];
__device__ unsigned gCntB[32];
__device__ unsigned gCntAll;

__constant__ int cPK[36] = {0,0,0,0,0,0,0,0, 1,1,1,1,1,1,1, 2,2,2,2,2,2,
                            3,3,3,3,3, 4,4,4,4, 5,5,5, 6,6, 7};
__constant__ int cPJ[36] = {0,1,2,3,4,5,6,7, 1,2,3,4,5,6,7, 2,3,4,5,6,7,
                            3,4,5,6,7, 4,5,6,7, 5,6,7, 6,7, 7};
__constant__ int cDiag[8] = {0,8,15,21,26,30,33,35};

__device__ __forceinline__ unsigned pk(float hi, float lo) {
    unsigned r;
    asm("cvt.rn.bf16x2.f32 %0, %1, %2;" : "=r"(r) : "f"(hi), "f"(lo));
    return r;
}

__device__ __forceinline__ void procE(float x, float& u, float& w,
                                      float& s1, float& s2) {
    float e = __expf(-x);
    float tt = 1.f + e;
    float nlp = __logf(tt);
    float r;
    asm("rcp.approx.ftz.f32 %0, %1;" : "=f"(r) : "f"(tt));
    float p2 = r * r;                     // sigmoid(x)^2
    u = fmaf(4.f, nlp, -x);
    w = p2 * x;
    s1 += nlp + x;
    s2 = fmaf(p2, fmaf(0.9f, x, nlp), s2);
}

__global__ void __launch_bounds__(256, 4)
fused_kernel(const float* __restrict__ logits, const float* __restrict__ labels,
             const float* __restrict__ olg, const float* __restrict__ otg,
             const float* __restrict__ att, const float* __restrict__ exist,
             float* __restrict__ out, int out_size) {
    __shared__ alignas(16) float satt[2048];   // 16B-aligned: float4 staged
    __shared__ float sAcc[SLOT];
    __shared__ float red[SLOT];
    __shared__ float csh[64];
    __shared__ float dpv[256];
    __shared__ int   chx[256];
    __shared__ float snrm[8];
    __shared__ int   scol[8];
    __shared__ int   sIsLast;

    const int tid = threadIdx.x;
    const int b = blockIdx.y, c = blockIdx.x;
    if (tid < SLOT) sAcc[tid] = 0.f;
    __syncthreads();

    const int t0 = c * TPB_T;
    const float* lg = logits + (size_t)b * 32768 * 8;
    const float* yb = labels + (size_t)b * 32768 * 8;

    // ---- overlap MSE (coalesced float4) ----
    const float* ob = olg + (size_t)b * 32768 + t0;
    const float* tb = otg + (size_t)b * 32768 + t0;
    float ov = 0.f;
    for (int i = tid; i < TPB_T / 4; i += 256) {
        float4 o4 = reinterpret_cast<const float4*>(ob)[i];
        float4 t4 = reinterpret_cast<const float4*>(tb)[i];
        float d0 = o4.x - t4.x, d1 = o4.y - t4.y;
        float d2 = o4.z - t4.z, d3 = o4.w - t4.w;
        ov = fmaf(d0, d0, fmaf(d1, d1, fmaf(d2, d2, fmaf(d3, d3, ov))));
    }

    // ---- streaming mma pass: warp covers 256 t's as 16 steps of 16 ----
    const int wrp = tid >> 5, l = tid & 31;
    const int gid = l >> 2, tg = l & 3;
    const int tw = t0 + wrp * 256;
    const float* xp = lg + (size_t)tw * 8 + gid;
    const float* yp = yb + (size_t)tw * 8 + gid;
    const int o0 = 16 * tg, o1 = o0 + 8, o2 = o0 + 64, o3 = o0 + 72;

    float c0 = 0.f, c1 = 0.f, c2 = 0.f, c3 = 0.f, s1 = 0.f, s2 = 0.f;

#pragma unroll 4
    for (int i = 0; i < 16; i++) {
        const int base = i * 128;
        float x0 = xp[base + o0], x1 = xp[base + o1];
        float x2 = xp[base + o2], x3 = xp[base + o3];
        float y0 = yp[base + o0], y1 = yp[base + o1];
        float y2 = yp[base + o2], y3 = yp[base + o3];
        float u0, u1, u2, u3, w0, w1, w2, w3;
        procE(x0, u0, w0, s1, s2);
        procE(x1, u1, w1, s1, s2);
        procE(x2, u2, w2, s1, s2);
        procE(x3, u3, w3, s1, s2);
        unsigned a0 = pk(u1, u0), a1 = pk(w1, w0);
        unsigned a2 = pk(u3, u2), a3 = pk(w3, w2);
        unsigned bb0 = pk(y1, y0), bb1 = pk(y3, y2);
        asm("mma.sync.aligned.m16n8k16.row.col.f32.bf16.bf16.f32 "
            "{%0,%1,%2,%3}, {%4,%5,%6,%7}, {%8,%9}, {%0,%1,%2,%3};"
            : "+f"(c0), "+f"(c1), "+f"(c2), "+f"(c3)
            : "r"(a0), "r"(a1), "r"(a2), "r"(a3), "r"(bb0), "r"(bb1));
    }

    s1 += __shfl_xor_sync(FULLMASK, s1, 1);
    s1 += __shfl_xor_sync(FULLMASK, s1, 2);
    s2 += __shfl_xor_sync(FULLMASK, s2, 1);
    s2 += __shfl_xor_sync(FULLMASK, s2, 2);
#pragma unroll
    for (int off = 16; off >= 1; off >>= 1) ov += __shfl_down_sync(FULLMASK, ov, off);

    atomicAdd(&sAcc[gid * 8 + 2 * tg],          c0);
    atomicAdd(&sAcc[gid * 8 + 2 * tg + 1],      c1);
    atomicAdd(&sAcc[64 + gid * 8 + 2 * tg],     c2);
    atomicAdd(&sAcc[64 + gid * 8 + 2 * tg + 1], c3);
    if (tg == 0) {
        atomicAdd(&sAcc[128 + gid], s1);
        atomicAdd(&sAcc[136 + gid], s2);
    }
    if (l == 0) atomicAdd(&sAcc[144], ov);
    __syncthreads();

    if (tid < SLOT) gPart[(b * CHUNKS + c) * SLOT + tid] = sAcc[tid];

    // ---- gram + existence: only chunk-0 blocks ----
    if (c == 0) {
        const float4* ap = reinterpret_cast<const float4*>(att + (size_t)b * 2048);
        reinterpret_cast<float4*>(satt)[tid]       = ap[tid];
        reinterpret_cast<float4*>(satt)[256 + tid] = ap[256 + tid];
        __syncthreads();
        // warp-per-pair, no big register arrays
        for (int p = wrp; p < 36; p += 8) {
            const float* rk = satt + cPK[p] * 256 + l;
            const float* rj = satt + cPJ[p] * 256 + l;
            float s = 0.f;
#pragma unroll
            for (int m = 0; m < 8; m++) s = fmaf(rk[32 * m], rj[32 * m], s);
#pragma unroll
            for (int off = 16; off >= 1; off >>= 1) s += __shfl_down_sync(FULLMASK, s, off);
            if (l == 0) gGram[b * 40 + p] = s;
        }
        if (wrp == 0) {
            float v = 0.f;
            if (l < 8) {
                float e  = exist[b * 8 + l];
                float ll = __logf(1.f + __expf(-fabsf(e)));
                float spn = ll + fmaxf(-e, 0.f);
                float spp = ll + fmaxf(e, 0.f);
                v = 4.5f * spn + 0.1f * spp;
            }
            v += __shfl_down_sync(FULLMASK, v, 4);
            v += __shfl_down_sync(FULLMASK, v, 2);
            v += __shfl_down_sync(FULLMASK, v, 1);
            if (l == 0) gGram[b * 40 + 36] = v;
        }
    }

    // ---- last-arrival per batch ----
    // RELEASE: all block global stores (gPart, gGram) ordered before arrival:
    // barrier, THEN fence, THEN atomic.
    __syncthreads();
    if (tid == 0) {
        __threadfence();
        unsigned old = atomicAdd(&gCntB[b], 1u);
        sIsLast = (((old + 1u) & 15u) == 0u) ? 1 : 0;
    }
    __syncthreads();
    if (!sIsLast) return;
    __threadfence();   // ACQUIRE: order counter observation before gPart/gGram reads

    if (tid < SLOT) {
        float s = 0.f;
#pragma unroll
        for (int cc = 0; cc < CHUNKS; cc++) s += gPart[(b * CHUNKS + cc) * SLOT + tid];
        red[tid] = s;
    }
    __syncthreads();
    if (tid >= 32) return;

    // ======== warp-0 epilogue, lane-parallel ========
    const int lane = tid;

    // cost matrix
    for (int e = lane; e < 64; e += 32) {
        int k = e >> 3;
        float cc = (red[128 + k] + red[e]) * (1.f / 32768.f);
        if (!(fabsf(cc) <= 1e30f)) cc = 100.f;
        csh[e] = cc;
    }
    // norms from gram diagonal
    if (lane < 8) snrm[lane] = fmaxf(sqrtf(gGram[b * 40 + cDiag[lane]]), 1e-12f);
    if (lane == 0) dpv[0] = 0.f;
    __syncwarp();

    // ortho + contrast (lane-parallel divides)
    float o = 0.f, ct = 0.f;
    for (int p = lane; p < 36; p += 32) {
        float s = gGram[b * 40 + p] / (snrm[cPK[p]] * snrm[cPJ[p]]);
        if (cPK[p] == cPJ[p]) { float d = s - 1.f; o += d * d; }
        else { o += 2.f * s * s; ct += 2.f * fmaxf(s + 0.5f, 0.f); }
    }
#pragma unroll
    for (int off = 16; off >= 1; off >>= 1) {
        o  += __shfl_down_sync(FULLMASK, o,  off);
        ct += __shfl_down_sync(FULLMASK, ct, off);
    }

    // subset-DP: lane owns masks lane*8..lane*8+7, level-synchronous
    for (int r = 1; r <= 8; r++) {
        __syncwarp();
#pragma unroll
        for (int q = 0; q < 8; q++) {
            int m = lane * 8 + q;
            if (m >= 1 && __popc(m) == r) {
                float best = 1e30f; int bn = 0;
#pragma unroll
                for (int n = 0; n < 8; n++) {
                    if (m & (1 << n)) {
                        float v = dpv[m ^ (1 << n)] + csh[(r - 1) * 8 + n];
                        if (v < best) { best = v; bn = n; }
                    }
                }
                dpv[m] = best; chx[m] = bn;
            }
        }
    }
    __syncwarp();
    if (lane == 0) {
        int mask = 255;
        for (int r = 7; r >= 0; --r) { int n = chx[mask]; scol[r] = n; mask ^= (1 << n); }
    }
    __syncwarp();

    float asn = 0.f;
    if (lane < 8)
        asn = 0.75f * (red[136 + lane] - 0.8f * red[64 + lane * 8 + scol[lane]]);
    asn += __shfl_down_sync(FULLMASK, asn, 4);
    asn += __shfl_down_sync(FULLMASK, asn, 2);
    asn += __shfl_down_sync(FULLMASK, asn, 1);

    int lastAll = 0;
    if (lane == 0) {
        float exq = gGram[b * 40 + 36];
        float contrib = asn * (1.f / 8388608.f)
                      + exq * (1.f / 256.f)
                      + 0.1f * o  * (1.f / 2048.f)
                      + 0.1f * ct * (1.f / 1792.f)
                      + 0.5f * red[144] * (1.f / 1048576.f);
        gOut[b] = contrib;
        __threadfence();
        unsigned old2 = atomicAdd(&gCntAll, 1u);
        lastAll = (((old2 + 1u) & 31u) == 0u) ? 1 : 0;
    }
    lastAll = __shfl_sync(FULLMASK, lastAll, 0);
    if (!lastAll) return;
    __threadfence();

    float v = gOut[lane];
#pragma unroll
    for (int off = 16; off >= 1; off >>= 1) v += __shfl_down_sync(FULLMASK, v, off);
    float total = __shfl_sync(FULLMASK, v, 0);
    for (int i = lane; i < out_size; i += 32) out[i] = total;
}

extern "C" void kernel_launch(void* const* d_in, const int* in_sizes, int n_in,
                              void* d_out, int out_size) {
    const float* logits    = (const float*)d_in[0];
    const float* existence = (const float*)d_in[1];
    const float* attract   = (const float*)d_in[2];
    const float* labels    = (const float*)d_in[3];
    const float* olg       = (const float*)d_in[4];
    const float* otg       = (const float*)d_in[5];
    float* out = (float*)d_out;

    dim3 grid(CHUNKS, 32);
    fused_kernel<<<grid, 256>>>(logits, labels, olg, otg,
                                attract, existence, out, out_size);
}